// round 1
// baseline (speedup 1.0000x reference)
#include <cuda_runtime.h>
#include <cuda_bf16.h>

// dynFilter: out[b,1,h,w] = tanh( sum_{c,ky,kx} x[b,c,h+ky-2,w+kx-2] * filt[b, c*25+ky*5+kx, h, w] )
// Shapes: x [8,4,256,256] f32, filt [8,100,256,256] f32, out [8,1,256,256] f32.
// HBM-bound: ~210 MB compulsory traffic (filt streamed once). Strategy:
//   - CTA = (b, 4-row tile). 256 threads, each thread -> 4 consecutive w (float4).
//   - filt read as coalesced LDG.128 (100 per thread), the dominant stream.
//   - x staged in shared memory with halo, then per-channel 5x8 register window
//     reused across the 25 filt planes (no redundant DRAM x traffic).

#define KK 5
#define PADK 2
#define CC 4
#define HH 256
#define WW 256
#define TILE_H 4
#define NROWS (TILE_H + 2 * PADK)   // 8 halo rows
#define NCOLS (WW + 2 * PADK)       // 260 halo cols
#define NCOLS_PAD 264               // padded row stride in smem

__global__ __launch_bounds__(256, 4)
void dynfilter_kernel(const float* __restrict__ x,
                      const float* __restrict__ filt,
                      float* __restrict__ out)
{
    const int b  = blockIdx.y;
    const int h0 = blockIdx.x * TILE_H;
    const int tid = threadIdx.x;

    __shared__ float xs[CC][NROWS][NCOLS_PAD];

    // Cooperative halo load of x tile: rows h0-2 .. h0+5, cols -2 .. 257 (zero pad OOB).
    for (int idx = tid; idx < CC * NROWS * NCOLS; idx += 256) {
        int c   = idx / (NROWS * NCOLS);
        int rem = idx % (NROWS * NCOLS);
        int r   = rem / NCOLS;
        int col = rem % NCOLS;
        int gr = h0 - PADK + r;
        int gc = col - PADK;
        float v = 0.0f;
        if (gr >= 0 && gr < HH && gc >= 0 && gc < WW)
            v = x[(((b * CC) + c) * HH + gr) * WW + gc];
        xs[c][r][col] = v;
    }
    __syncthreads();

    const int hr = tid >> 6;     // 0..3  (row within tile)
    const int q  = tid & 63;     // 0..63 (float4 index within row)
    const int w  = q << 2;       // output w base
    const int h  = h0 + hr;

    float acc0 = 0.f, acc1 = 0.f, acc2 = 0.f, acc3 = 0.f;

    const float4* __restrict__ filt4 = (const float4*)filt;
    // filt element [b, p, h, w] -> float4 index ((b*100 + p)*256 + h)*64 + q
    const long plane = (long)(HH * WW / 4);              // 16384
    long base = ((long)b * (CC * KK * KK) * HH + h) * (WW / 4) + q;

    #pragma unroll
    for (int c = 0; c < CC; ++c) {
        // Register window: 5 rows x 8 cols covers kx in [0,4] for 4 outputs.
        float xr[KK][8];
        #pragma unroll
        for (int ky = 0; ky < KK; ++ky) {
            #pragma unroll
            for (int j = 0; j < 8; ++j)
                xr[ky][j] = xs[c][hr + ky][w + j];
        }
        #pragma unroll
        for (int ky = 0; ky < KK; ++ky) {
            #pragma unroll
            for (int kx = 0; kx < KK; ++kx) {
                const int p = (c * KK + ky) * KK + kx;
                const float4 f = __ldg(&filt4[base + (long)p * plane]);
                acc0 = fmaf(xr[ky][kx + 0], f.x, acc0);
                acc1 = fmaf(xr[ky][kx + 1], f.y, acc1);
                acc2 = fmaf(xr[ky][kx + 2], f.z, acc2);
                acc3 = fmaf(xr[ky][kx + 3], f.w, acc3);
            }
        }
    }

    float4 o;
    o.x = tanhf(acc0);
    o.y = tanhf(acc1);
    o.z = tanhf(acc2);
    o.w = tanhf(acc3);
    ((float4*)out)[((long)b * HH + h) * (WW / 4) + q] = o;
}

extern "C" void kernel_launch(void* const* d_in, const int* in_sizes, int n_in,
                              void* d_out, int out_size)
{
    const float* x    = (const float*)d_in[0];   // [8,4,256,256]
    const float* filt = (const float*)d_in[1];   // [8,100,256,256]
    float* out        = (float*)d_out;           // [8,1,256,256]

    dim3 grid(HH / TILE_H, 8);   // 64 x 8 = 512 CTAs
    dim3 block(256);
    dynfilter_kernel<<<grid, block>>>(x, filt, out);
}

// round 2
// speedup vs baseline: 1.1522x; 1.1522x over previous
#include <cuda_runtime.h>
#include <cuda_bf16.h>

// dynFilter: out[b,1,h,w] = tanh( sum_{c,ky,kx} x[b,c,h+ky-2,w+kx-2] * filt[b, c*25+ky*5+kx, h, w] )
// x [8,4,256,256] f32, filt [8,100,256,256] f32, out [8,1,256,256] f32.
// HBM-bound (~210 MB compulsory). R1 fix: 128-thr CTAs (4 rows x 128 cols),
// 8 CTAs/SM (50% occ), balanced single wave of 1024 CTAs, vectorized LDS.128
// smem window reads, front-batched filt LDG.128 per ky row.

#define KK 5
#define PADK 2
#define CC 4
#define HH 256
#define WW 256
#define TILE_H 4
#define TILE_W 128
#define NROWS (TILE_H + 2 * PADK)        // 8 halo rows
#define NCOLS (TILE_W + 2 * PADK)        // 132 halo cols
#define NCOLS_PAD 136                    // 16B-aligned row stride

__global__ __launch_bounds__(128, 8)
void dynfilter_kernel(const float* __restrict__ x,
                      const float* __restrict__ filt,
                      float* __restrict__ out)
{
    const int b     = blockIdx.z;
    const int whalf = blockIdx.y;            // 0..1
    const int h0    = blockIdx.x * TILE_H;   // tile row base
    const int w0    = whalf * TILE_W;        // tile col base
    const int tid   = threadIdx.x;

    __shared__ __align__(16) float xs[CC][NROWS][NCOLS_PAD];

    // Cooperative halo load: rows h0-2..h0+5, cols w0-2..w0+129 (zero pad OOB).
    #pragma unroll
    for (int it = 0; it < (CC * NROWS * NCOLS + 127) / 128; ++it) {
        int idx = it * 128 + tid;
        if (idx < CC * NROWS * NCOLS) {
            int c   = idx / (NROWS * NCOLS);
            int rem = idx % (NROWS * NCOLS);
            int r   = rem / NCOLS;
            int col = rem % NCOLS;
            int gr = h0 - PADK + r;
            int gc = w0 - PADK + col;
            float v = 0.0f;
            if (gr >= 0 && gr < HH && gc >= 0 && gc < WW)
                v = x[(((b * CC) + c) * HH + gr) * WW + gc];
            xs[c][r][col] = v;
        }
    }
    __syncthreads();

    const int hr = tid >> 5;       // 0..3 row within tile
    const int q  = tid & 31;       // 0..31 float4 column within tile
    const int h  = h0 + hr;
    const int wl = q << 2;         // local col (xs col index of first output's w-2)

    float acc0 = 0.f, acc1 = 0.f, acc2 = 0.f, acc3 = 0.f;

    const float4* __restrict__ filt4 = (const float4*)filt;
    const long plane = (long)(HH * WW / 4);  // 16384 float4 per plane
    long fbase = ((long)b * (CC * KK * KK) * HH + h) * (WW / 4) + (whalf * 32 + q);

    #pragma unroll
    for (int c = 0; c < CC; ++c) {
        // Register window: 5 rows x 8 cols via two conflict-free LDS.128 per row.
        float xr[KK][8];
        #pragma unroll
        for (int ky = 0; ky < KK; ++ky) {
            float4 a = *(const float4*)&xs[c][hr + ky][wl];
            float4 bb = *(const float4*)&xs[c][hr + ky][wl + 4];
            xr[ky][0] = a.x;  xr[ky][1] = a.y;  xr[ky][2] = a.z;  xr[ky][3] = a.w;
            xr[ky][4] = bb.x; xr[ky][5] = bb.y; xr[ky][6] = bb.z; xr[ky][7] = bb.w;
        }
        #pragma unroll
        for (int ky = 0; ky < KK; ++ky) {
            // Front-batch the 5 filt loads for this ky row (raise MLP).
            float4 f[KK];
            #pragma unroll
            for (int kx = 0; kx < KK; ++kx) {
                const int p = (c * KK + ky) * KK + kx;
                f[kx] = __ldg(&filt4[fbase + (long)p * plane]);
            }
            #pragma unroll
            for (int kx = 0; kx < KK; ++kx) {
                acc0 = fmaf(xr[ky][kx + 0], f[kx].x, acc0);
                acc1 = fmaf(xr[ky][kx + 1], f[kx].y, acc1);
                acc2 = fmaf(xr[ky][kx + 2], f[kx].z, acc2);
                acc3 = fmaf(xr[ky][kx + 3], f[kx].w, acc3);
            }
        }
    }

    float4 o;
    o.x = tanhf(acc0);
    o.y = tanhf(acc1);
    o.z = tanhf(acc2);
    o.w = tanhf(acc3);
    ((float4*)out)[((long)b * HH + h) * (WW / 4) + whalf * 32 + q] = o;
}

extern "C" void kernel_launch(void* const* d_in, const int* in_sizes, int n_in,
                              void* d_out, int out_size)
{
    const float* x    = (const float*)d_in[0];   // [8,4,256,256]
    const float* filt = (const float*)d_in[1];   // [8,100,256,256]
    float* out        = (float*)d_out;           // [8,1,256,256]

    dim3 grid(HH / TILE_H, WW / TILE_W, 8);   // 64 x 2 x 8 = 1024 CTAs
    dim3 block(128);
    dynfilter_kernel<<<grid, block>>>(x, filt, out);
}